// round 5
// baseline (speedup 1.0000x reference)
#include <cuda_runtime.h>

#define NN 50000
#define NE 500000
#define D 128
#define TDIM 32
#define EDIM 160
#define TE 128       // edges per block (E1 GEMM)
#define SA 164       // attr tile smem stride (words)
#define TNODE 64     // nodes per block (proj kernel)

// ---- scratch (no cudaMalloc allowed) ----
__device__ float g_q[NN * D];
__device__ float g_k[NN * D];
__device__ float g_v[NN * D];
__device__ float g_agg[NN * D];
__device__ float g_sum[NN * 2];
__device__ float g_e[(size_t)NE * D];      // 256MB edge projection scratch
__device__ unsigned g_we_sw[EDIM * D];     // pre-swizzled tf32 We
__device__ int   g_idx64;

// ---- helpers ----
__device__ __forceinline__ unsigned to_tf32(float f) {
    unsigned r;
    asm("cvt.rna.tf32.f32 %0, %1;" : "=r"(r) : "f"(f));
    return r;
}
__device__ __forceinline__ unsigned long long dup2(float w) {
    unsigned long long d;
    asm("mov.b64 %0, {%1, %1};" : "=l"(d) : "r"(__float_as_uint(w)));
    return d;
}
__device__ __forceinline__ void fma2(unsigned long long& d,
                                     unsigned long long a, unsigned long long b) {
    asm("fma.rn.f32x2 %0, %1, %2, %0;" : "+l"(d) : "l"(a), "l"(b));
}
__device__ __forceinline__ float lo32(unsigned long long v) {
    return __uint_as_float((unsigned)(v & 0xffffffffu));
}
__device__ __forceinline__ float hi32(unsigned long long v) {
    return __uint_as_float((unsigned)(v >> 32));
}
__device__ __forceinline__ void red_v4(float* p, float a, float b, float c, float d) {
    asm volatile("red.global.add.v4.f32 [%0], {%1,%2,%3,%4};"
                 :: "l"(p), "f"(a), "f"(b), "f"(c), "f"(d) : "memory");
}
__device__ __forceinline__ void red_1(float* p, float a) {
    asm volatile("red.global.add.f32 [%0], %1;" :: "l"(p), "f"(a) : "memory");
}
__device__ __forceinline__ void mma_tf32(float* c, const unsigned* a,
                                         unsigned b0, unsigned b1) {
    asm volatile(
        "mma.sync.aligned.m16n8k8.row.col.f32.tf32.tf32.f32 "
        "{%0,%1,%2,%3}, {%4,%5,%6,%7}, {%8,%9}, {%0,%1,%2,%3};"
        : "+f"(c[0]), "+f"(c[1]), "+f"(c[2]), "+f"(c[3])
        : "r"(a[0]), "r"(a[1]), "r"(a[2]), "r"(a[3]), "r"(b0), "r"(b1));
}

// Detect int64 vs int32 edge_index.
__global__ void detect_kernel(const long long* __restrict__ ei) {
    if (threadIdx.x == 0 && blockIdx.x == 0) {
        bool ok = true;
        #pragma unroll
        for (int i = 0; i < 16; i++) {
            long long v = ei[i];
            if (v < 0 || v >= NN) ok = false;
        }
        g_idx64 = ok ? 1 : 0;
    }
}

// Pre-swizzle We into tf32: within each 64-col half, col (ni*8+g) -> (g*8+ni).
__global__ void swizzle_we_kernel(const float* __restrict__ We) {
    int i = blockIdx.x * blockDim.x + threadIdx.x;
    if (i < EDIM * D) {
        const int k = i >> 7, c = i & 127;
        const int half = c >> 6, rem = c & 63;
        const int ni = rem >> 3, g = rem & 7;
        g_we_sw[k * D + half * 64 + g * 8 + ni] = to_tf32(__ldg(We + i));
    }
}

__global__ void zero_kernel() {
    int idx = blockIdx.x * blockDim.x + threadIdx.x;
    if (idx < NN * D) g_agg[idx] = 0.0f;
    if (idx < NN * 2) g_sum[idx] = 0.0f;
}

// ---- proj: q,k,v,skip = x @ W + b (FFMA2 tiled) ----
__global__ __launch_bounds__(256) void proj_kernel(
    const float* __restrict__ x,
    const float* __restrict__ Wq, const float* __restrict__ bq,
    const float* __restrict__ Wk, const float* __restrict__ bk,
    const float* __restrict__ Wv, const float* __restrict__ bv,
    const float* __restrict__ Ws, const float* __restrict__ bs,
    float* __restrict__ out)
{
    __shared__ float xT[D][TNODE];
    const int tid = threadIdx.x;
    const int n0  = blockIdx.x * TNODE;

    for (int i = tid; i < 32 * TNODE; i += 256) {
        const int q = i >> 6, e = i & 63;
        float4 m = make_float4(0, 0, 0, 0);
        if (n0 + e < NN) m = __ldg((const float4*)(x + (size_t)(n0 + e) * D) + q);
        xT[4 * q + 0][e] = m.x; xT[4 * q + 1][e] = m.y;
        xT[4 * q + 2][e] = m.z; xT[4 * q + 3][e] = m.w;
    }
    __syncthreads();

    const int lane = tid & 31, w = tid >> 5;
    const float* Wlist[4] = {Wq, Wk, Wv, Ws};
    const float* blist[4] = {bq, bk, bv, bs};
    float*       dlist[4] = {g_q, g_k, g_v, out};

    #pragma unroll
    for (int m = 0; m < 4; m++) {
        const float4* W4 = (const float4*)Wlist[m];
        unsigned long long acc[4][4];
        #pragma unroll
        for (int i = 0; i < 4; i++)
            #pragma unroll
            for (int j = 0; j < 4; j++) acc[i][j] = 0ull;

        #pragma unroll 4
        for (int k = 0; k < D; k++) {
            const double2* ap = (const double2*)(&xT[k][w * 8]);
            double2 p0 = ap[0], p1 = ap[1];
            unsigned long long a0 = __double_as_longlong(p0.x);
            unsigned long long a1 = __double_as_longlong(p0.y);
            unsigned long long a2 = __double_as_longlong(p1.x);
            unsigned long long a3 = __double_as_longlong(p1.y);
            const float4 wv = __ldg(W4 + k * 32 + lane);
            unsigned long long w0 = dup2(wv.x), w1 = dup2(wv.y),
                               w2 = dup2(wv.z), w3 = dup2(wv.w);
            fma2(acc[0][0], a0, w0); fma2(acc[0][1], a0, w1);
            fma2(acc[0][2], a0, w2); fma2(acc[0][3], a0, w3);
            fma2(acc[1][0], a1, w0); fma2(acc[1][1], a1, w1);
            fma2(acc[1][2], a1, w2); fma2(acc[1][3], a1, w3);
            fma2(acc[2][0], a2, w0); fma2(acc[2][1], a2, w1);
            fma2(acc[2][2], a2, w2); fma2(acc[2][3], a2, w3);
            fma2(acc[3][0], a3, w0); fma2(acc[3][1], a3, w1);
            fma2(acc[3][2], a3, w2); fma2(acc[3][3], a3, w3);
        }

        const float4 bb = __ldg((const float4*)blist[m] + lane);
        float* dst = dlist[m];
        #pragma unroll
        for (int i = 0; i < 4; i++) {
            const int nA = n0 + w * 8 + i * 2;
            if (nA < NN) {
                float4 o = make_float4(lo32(acc[i][0]) + bb.x, lo32(acc[i][1]) + bb.y,
                                       lo32(acc[i][2]) + bb.z, lo32(acc[i][3]) + bb.w);
                *(float4*)(dst + (size_t)nA * D + lane * 4) = o;
            }
            if (nA + 1 < NN) {
                float4 o = make_float4(hi32(acc[i][0]) + bb.x, hi32(acc[i][1]) + bb.y,
                                       hi32(acc[i][2]) + bb.z, hi32(acc[i][3]) + bb.w);
                *(float4*)(dst + (size_t)(nA + 1) * D + lane * 4) = o;
            }
        }
    }
}

// ---- E1: e = attr @ We (tf32 mma, pre-swizzled B via LDG.128) ----
__global__ __launch_bounds__(256, 2) void egemm_kernel(
    const void*  __restrict__ ei_raw,
    const float* __restrict__ last_update,
    const float* __restrict__ t,
    const float* __restrict__ msg,
    const float* __restrict__ time_w,
    const float* __restrict__ time_b)
{
    extern __shared__ unsigned sA[];    // [TE][SA] tf32 attr tile (84KB)
    __shared__ float s_rel[TE];

    const int tid = threadIdx.x;
    const int e0  = blockIdx.x * TE;

    // phase 1: rel time per edge
    if (tid < TE) {
        const int eg = e0 + tid;
        float rel = 0.f;
        if (eg < NE) {
            int src;
            if (g_idx64) src = (int)__ldg((const long long*)ei_raw + eg);
            else         src = __ldg((const int*)ei_raw + eg);
            rel = __ldg(last_update + src) - __ldg(t + eg);
        }
        s_rel[tid] = rel;
    }
    __syncthreads();

    // phase 2: build attr tile (tf32)
    for (int i = tid; i < TE * TDIM; i += 256) {          // time-encode cols [0,32)
        const int e = i >> 5, k = i & 31;
        float v = 0.f;
        if (e0 + e < NE)
            v = cosf(s_rel[e] * __ldg(time_w + k) + __ldg(time_b + k));
        sA[e * SA + k] = to_tf32(v);
    }
    for (int i = tid; i < TE * 32; i += 256) {            // msg cols [32,160)
        const int e = i >> 5, q = i & 31;
        float4 m = make_float4(0, 0, 0, 0);
        if (e0 + e < NE) m = __ldg((const float4*)(msg + (size_t)(e0 + e) * D) + q);
        unsigned* p = sA + e * SA + TDIM + 4 * q;
        p[0] = to_tf32(m.x); p[1] = to_tf32(m.y);
        p[2] = to_tf32(m.z); p[3] = to_tf32(m.w);
    }
    __syncthreads();

    // phase 3: GEMM. 8 warps: 4(M) x 2(N); warp tile 32x64.
    const int wid = tid >> 5, lane = tid & 31;
    const int g = lane >> 2, tg = lane & 3;
    const int wm = wid & 3, wn = wid >> 2;

    float acc[2][8][4];
    #pragma unroll
    for (int mi = 0; mi < 2; mi++)
        #pragma unroll
        for (int ni = 0; ni < 8; ni++)
            #pragma unroll
            for (int r = 0; r < 4; r++) acc[mi][ni][r] = 0.f;

    const unsigned* Abase = sA + (wm * 32 + g) * SA + tg;
    const unsigned* Bb    = g_we_sw + wn * 64 + g * 8;    // thread's swizzled B base

    #pragma unroll 2
    for (int ks = 0; ks < EDIM / 8; ks++) {
        const int k0 = ks * 8;
        unsigned a[2][4];
        #pragma unroll
        for (int mi = 0; mi < 2; mi++) {
            const unsigned* ap = Abase + mi * 16 * SA + k0;
            a[mi][0] = ap[0];
            a[mi][1] = ap[8 * SA];
            a[mi][2] = ap[4];
            a[mi][3] = ap[8 * SA + 4];
        }
        const uint4* p0 = (const uint4*)(Bb + (k0 + tg) * D);
        const uint4* p1 = (const uint4*)(Bb + (k0 + tg + 4) * D);
        const uint4 b0lo = __ldg(p0), b0hi = __ldg(p0 + 1);
        const uint4 b1lo = __ldg(p1), b1hi = __ldg(p1 + 1);
        const unsigned b0[8] = {b0lo.x, b0lo.y, b0lo.z, b0lo.w,
                                b0hi.x, b0hi.y, b0hi.z, b0hi.w};
        const unsigned b1[8] = {b1lo.x, b1lo.y, b1lo.z, b1lo.w,
                                b1hi.x, b1hi.y, b1hi.z, b1hi.w};
        #pragma unroll
        for (int ni = 0; ni < 8; ni++) {
            mma_tf32(acc[0][ni], a[0], b0[ni], b1[ni]);
            mma_tf32(acc[1][ni], a[1], b0[ni], b1[ni]);
        }
    }

    // phase 4: write e tile to gmem
    #pragma unroll
    for (int mi = 0; mi < 2; mi++) {
        const int r0 = wm * 32 + mi * 16 + g;
        #pragma unroll
        for (int ni = 0; ni < 8; ni++) {
            const int c = wn * 64 + ni * 8 + 2 * tg;
            if (e0 + r0 < NE)
                *(float2*)(g_e + (size_t)(e0 + r0) * D + c) =
                    make_float2(acc[mi][ni][0], acc[mi][ni][1]);
            if (e0 + r0 + 8 < NE)
                *(float2*)(g_e + (size_t)(e0 + r0 + 8) * D + c) =
                    make_float2(acc[mi][ni][2], acc[mi][ni][3]);
        }
    }
}

// ---- E2: attention epilogue. Warp handles 8 edges; lane owns 4 cols. ----
__global__ __launch_bounds__(256) void epilogue_kernel(
    const void* __restrict__ ei_raw)
{
    const int tid  = threadIdx.x;
    const int w    = tid >> 5, lane = tid & 31;
    const int col  = lane * 4;
    const int e0   = blockIdx.x * 64 + w * 8;

    #pragma unroll 2
    for (int ii = 0; ii < 8; ii++) {
        const int eg = e0 + ii;
        if (eg < NE) {
            int src, dst;
            if (g_idx64) {
                const long long* p = (const long long*)ei_raw;
                src = (int)__ldg(p + eg); dst = (int)__ldg(p + NE + eg);
            } else {
                const int* p = (const int*)ei_raw;
                src = __ldg(p + eg); dst = __ldg(p + NE + eg);
            }
            const float4 ev = __ldg((const float4*)(g_e + (size_t)eg * D) + lane);
            const float4 qi = *(const float4*)(g_q + (size_t)dst * D + col);
            float4 kj = *(const float4*)(g_k + (size_t)src * D + col);
            float4 vj = *(const float4*)(g_v + (size_t)src * D + col);
            kj.x += ev.x; kj.y += ev.y; kj.z += ev.z; kj.w += ev.w;
            vj.x += ev.x; vj.y += ev.y; vj.z += ev.z; vj.w += ev.w;

            float p = qi.x * kj.x + qi.y * kj.y + qi.z * kj.z + qi.w * kj.w;
            p += __shfl_xor_sync(0xffffffffu, p, 1);
            p += __shfl_xor_sync(0xffffffffu, p, 2);
            p += __shfl_xor_sync(0xffffffffu, p, 4);
            p += __shfl_xor_sync(0xffffffffu, p, 8);
            const float ex = expf(p * 0.125f);   // 1/sqrt(64); exact softmax w/o max-sub

            red_v4(g_agg + (size_t)dst * D + col,
                   ex * vj.x, ex * vj.y, ex * vj.z, ex * vj.w);
            if ((lane & 15) == 0)
                red_1(&g_sum[dst * 2 + (lane >> 4)], ex);
        }
    }
}

__global__ void finalize_kernel(float* __restrict__ out) {
    int idx = blockIdx.x * blockDim.x + threadIdx.x;
    if (idx >= NN * 32) return;
    const int n = idx >> 5;
    const int h = (idx & 31) >> 4;
    const float inv = 1.0f / (g_sum[n * 2 + h] + 1e-16f);
    float4 a = ((const float4*)g_agg)[idx];
    float4 o = ((float4*)out)[idx];
    o.x += a.x * inv; o.y += a.y * inv; o.z += a.z * inv; o.w += a.w * inv;
    ((float4*)out)[idx] = o;
}

extern "C" void kernel_launch(void* const* d_in, const int* in_sizes, int n_in,
                              void* d_out, int out_size) {
    const float* x           = (const float*)d_in[0];
    const float* last_update = (const float*)d_in[1];
    const void*  ei          = d_in[2];
    const float* t           = (const float*)d_in[3];
    const float* msg         = (const float*)d_in[4];
    const float* time_w      = (const float*)d_in[5];
    const float* time_b      = (const float*)d_in[6];
    const float* Wq          = (const float*)d_in[7];
    const float* bq          = (const float*)d_in[8];
    const float* Wk          = (const float*)d_in[9];
    const float* bk          = (const float*)d_in[10];
    const float* Wv          = (const float*)d_in[11];
    const float* bv          = (const float*)d_in[12];
    const float* We          = (const float*)d_in[13];
    const float* Ws          = (const float*)d_in[14];
    const float* bs          = (const float*)d_in[15];
    float* out = (float*)d_out;

    const int smem_e1 = TE * SA * 4;   // 83,968 bytes
    static int configured = 0;
    if (!configured) {
        cudaFuncSetAttribute(egemm_kernel,
                             cudaFuncAttributeMaxDynamicSharedMemorySize, smem_e1);
        configured = 1;
    }

    detect_kernel<<<1, 32>>>((const long long*)ei);
    swizzle_we_kernel<<<(EDIM * D + 255) / 256, 256>>>(We);
    zero_kernel<<<(NN * D + 255) / 256, 256>>>();
    proj_kernel<<<(NN + TNODE - 1) / TNODE, 256>>>(x, Wq, bq, Wk, bk, Wv, bv, Ws, bs, out);
    egemm_kernel<<<(NE + TE - 1) / TE, 256, smem_e1>>>(ei, last_update, t, msg,
                                                       time_w, time_b);
    epilogue_kernel<<<(NE + 63) / 64, 256>>>(ei);
    finalize_kernel<<<(NN * 32 + 255) / 256, 256>>>(out);
}

// round 6
// speedup vs baseline: 1.2170x; 1.2170x over previous
#include <cuda_runtime.h>
#include <cuda_fp16.h>

#define NN 50000
#define NE 500000
#define D 128
#define TDIM 32
#define EDIM 160
#define TE 128       // edges per block (E1 GEMM)
#define SA 164       // attr tile smem stride (words)
#define SX 132       // x tile smem stride (words, proj mma)

// ---- scratch (no cudaMalloc allowed) ----
__device__ float g_q[NN * D];
__device__ float g_k[NN * D];
__device__ float g_v[NN * D];
__device__ float g_agg[NN * D];
__device__ float g_sum[NN * 2];
__device__ __half2 g_e[(size_t)NE * 64];   // 128MB fp16 edge projection scratch
__device__ unsigned g_we_sw[EDIM * D];     // pre-swizzled tf32 We
__device__ unsigned g_w_sw[4 * D * D];     // pre-swizzled tf32 Wq|Wk|Wv|Wskip
__device__ int   g_idx64;

// ---- helpers ----
__device__ __forceinline__ unsigned to_tf32(float f) {
    unsigned r;
    asm("cvt.rna.tf32.f32 %0, %1;" : "=r"(r) : "f"(f));
    return r;
}
__device__ __forceinline__ void red_v4(float* p, float a, float b, float c, float d) {
    asm volatile("red.global.add.v4.f32 [%0], {%1,%2,%3,%4};"
                 :: "l"(p), "f"(a), "f"(b), "f"(c), "f"(d) : "memory");
}
__device__ __forceinline__ void red_1(float* p, float a) {
    asm volatile("red.global.add.f32 [%0], %1;" :: "l"(p), "f"(a) : "memory");
}
__device__ __forceinline__ void mma_tf32(float* c, const unsigned* a,
                                         unsigned b0, unsigned b1) {
    asm volatile(
        "mma.sync.aligned.m16n8k8.row.col.f32.tf32.tf32.f32 "
        "{%0,%1,%2,%3}, {%4,%5,%6,%7}, {%8,%9}, {%0,%1,%2,%3};"
        : "+f"(c[0]), "+f"(c[1]), "+f"(c[2]), "+f"(c[3])
        : "r"(a[0]), "r"(a[1]), "r"(a[2]), "r"(a[3]), "r"(b0), "r"(b1));
}

// Detect int64 vs int32 edge_index.
__global__ void detect_kernel(const long long* __restrict__ ei) {
    if (threadIdx.x == 0 && blockIdx.x == 0) {
        bool ok = true;
        #pragma unroll
        for (int i = 0; i < 16; i++) {
            long long v = ei[i];
            if (v < 0 || v >= NN) ok = false;
        }
        g_idx64 = ok ? 1 : 0;
    }
}

// Pre-swizzle We into tf32: within each 64-col half, col (ni*8+g) -> (g*8+ni).
__global__ void swizzle_we_kernel(const float* __restrict__ We) {
    int i = blockIdx.x * blockDim.x + threadIdx.x;
    if (i < EDIM * D) {
        const int k = i >> 7, c = i & 127;
        const int half = c >> 6, rem = c & 63;
        const int ni = rem >> 3, g = rem & 7;
        g_we_sw[k * D + half * 64 + g * 8 + ni] = to_tf32(__ldg(We + i));
    }
}

// Pre-swizzle the four node-projection weights.
__global__ void swizzle_w_kernel(const float* __restrict__ Wq,
                                 const float* __restrict__ Wk,
                                 const float* __restrict__ Wv,
                                 const float* __restrict__ Ws) {
    int i = blockIdx.x * blockDim.x + threadIdx.x;
    if (i < 4 * D * D) {
        const int mat = i >> 14, rem = i & 16383;
        const int k = rem >> 7, c = rem & 127;
        const int half = c >> 6, r2 = c & 63;
        const int ni = r2 >> 3, g = r2 & 7;
        const float* W = (mat == 0) ? Wq : (mat == 1) ? Wk : (mat == 2) ? Wv : Ws;
        g_w_sw[mat * D * D + k * D + half * 64 + g * 8 + ni] = to_tf32(__ldg(W + rem));
    }
}

__global__ void zero_kernel() {
    int idx = blockIdx.x * blockDim.x + threadIdx.x;
    if (idx < NN * D) g_agg[idx] = 0.0f;
    if (idx < NN * 2) g_sum[idx] = 0.0f;
}

// ---- proj (tf32 mma): q,k,v,skip = x @ W + b. grid = (nodeTiles, 4 mats) ----
__global__ __launch_bounds__(256, 2) void proj_kernel(
    const float* __restrict__ x,
    const float* __restrict__ bq, const float* __restrict__ bk,
    const float* __restrict__ bv, const float* __restrict__ bs,
    float* __restrict__ out)
{
    extern __shared__ unsigned sX[];   // [128][SX] tf32 x tile (67.6KB)
    const int tid = threadIdx.x;
    const int n0  = blockIdx.x * 128;
    const int mat = blockIdx.y;

    // stage x tile as tf32
    for (int i = tid; i < 128 * 32; i += 256) {
        const int n = i >> 5, q = i & 31;
        float4 m = make_float4(0, 0, 0, 0);
        if (n0 + n < NN) m = __ldg((const float4*)(x + (size_t)(n0 + n) * D) + q);
        unsigned* p = sX + n * SX + 4 * q;
        p[0] = to_tf32(m.x); p[1] = to_tf32(m.y);
        p[2] = to_tf32(m.z); p[3] = to_tf32(m.w);
    }
    __syncthreads();

    const int wid = tid >> 5, lane = tid & 31;
    const int g = lane >> 2, tg = lane & 3;
    const int wm = wid & 3, wn = wid >> 2;

    float acc[2][8][4];
    #pragma unroll
    for (int mi = 0; mi < 2; mi++)
        #pragma unroll
        for (int ni = 0; ni < 8; ni++)
            #pragma unroll
            for (int r = 0; r < 4; r++) acc[mi][ni][r] = 0.f;

    const unsigned* Abase = sX + (wm * 32 + g) * SX + tg;
    const unsigned* Bb    = g_w_sw + mat * D * D + wn * 64 + g * 8;

    #pragma unroll 2
    for (int ks = 0; ks < D / 8; ks++) {
        const int k0 = ks * 8;
        unsigned a[2][4];
        #pragma unroll
        for (int mi = 0; mi < 2; mi++) {
            const unsigned* ap = Abase + mi * 16 * SX + k0;
            a[mi][0] = ap[0];
            a[mi][1] = ap[8 * SX];
            a[mi][2] = ap[4];
            a[mi][3] = ap[8 * SX + 4];
        }
        const uint4* p0 = (const uint4*)(Bb + (k0 + tg) * D);
        const uint4* p1 = (const uint4*)(Bb + (k0 + tg + 4) * D);
        const uint4 b0lo = __ldg(p0), b0hi = __ldg(p0 + 1);
        const uint4 b1lo = __ldg(p1), b1hi = __ldg(p1 + 1);
        const unsigned b0[8] = {b0lo.x, b0lo.y, b0lo.z, b0lo.w,
                                b0hi.x, b0hi.y, b0hi.z, b0hi.w};
        const unsigned b1[8] = {b1lo.x, b1lo.y, b1lo.z, b1lo.w,
                                b1hi.x, b1hi.y, b1hi.z, b1hi.w};
        #pragma unroll
        for (int ni = 0; ni < 8; ni++) {
            mma_tf32(acc[0][ni], a[0], b0[ni], b1[ni]);
            mma_tf32(acc[1][ni], a[1], b0[ni], b1[ni]);
        }
    }

    const float* bias = (mat == 0) ? bq : (mat == 1) ? bk : (mat == 2) ? bv : bs;
    float* dst = (mat == 0) ? g_q : (mat == 1) ? g_k : (mat == 2) ? g_v : out;

    #pragma unroll
    for (int mi = 0; mi < 2; mi++) {
        const int r0 = n0 + wm * 32 + mi * 16 + g;
        #pragma unroll
        for (int ni = 0; ni < 8; ni++) {
            const int c = wn * 64 + ni * 8 + 2 * tg;
            const float2 bb = __ldg((const float2*)(bias + c));
            if (r0 < NN)
                *(float2*)(dst + (size_t)r0 * D + c) =
                    make_float2(acc[mi][ni][0] + bb.x, acc[mi][ni][1] + bb.y);
            if (r0 + 8 < NN)
                *(float2*)(dst + (size_t)(r0 + 8) * D + c) =
                    make_float2(acc[mi][ni][2] + bb.x, acc[mi][ni][3] + bb.y);
        }
    }
}

// ---- E1: e = attr @ We (tf32 mma, pre-swizzled B via LDG.128, fp16 out) ----
__global__ __launch_bounds__(256, 2) void egemm_kernel(
    const void*  __restrict__ ei_raw,
    const float* __restrict__ last_update,
    const float* __restrict__ t,
    const float* __restrict__ msg,
    const float* __restrict__ time_w,
    const float* __restrict__ time_b)
{
    extern __shared__ unsigned sA[];    // [TE][SA] tf32 attr tile (84KB)
    __shared__ float s_rel[TE];

    const int tid = threadIdx.x;
    const int e0  = blockIdx.x * TE;

    if (tid < TE) {
        const int eg = e0 + tid;
        float rel = 0.f;
        if (eg < NE) {
            int src;
            if (g_idx64) src = (int)__ldg((const long long*)ei_raw + eg);
            else         src = __ldg((const int*)ei_raw + eg);
            rel = __ldg(last_update + src) - __ldg(t + eg);
        }
        s_rel[tid] = rel;
    }
    __syncthreads();

    for (int i = tid; i < TE * TDIM; i += 256) {          // time-encode cols [0,32)
        const int e = i >> 5, k = i & 31;
        float v = 0.f;
        if (e0 + e < NE)
            v = cosf(s_rel[e] * __ldg(time_w + k) + __ldg(time_b + k));
        sA[e * SA + k] = to_tf32(v);
    }
    for (int i = tid; i < TE * 32; i += 256) {            // msg cols [32,160)
        const int e = i >> 5, q = i & 31;
        float4 m = make_float4(0, 0, 0, 0);
        if (e0 + e < NE) m = __ldg((const float4*)(msg + (size_t)(e0 + e) * D) + q);
        unsigned* p = sA + e * SA + TDIM + 4 * q;
        p[0] = to_tf32(m.x); p[1] = to_tf32(m.y);
        p[2] = to_tf32(m.z); p[3] = to_tf32(m.w);
    }
    __syncthreads();

    const int wid = tid >> 5, lane = tid & 31;
    const int g = lane >> 2, tg = lane & 3;
    const int wm = wid & 3, wn = wid >> 2;

    float acc[2][8][4];
    #pragma unroll
    for (int mi = 0; mi < 2; mi++)
        #pragma unroll
        for (int ni = 0; ni < 8; ni++)
            #pragma unroll
            for (int r = 0; r < 4; r++) acc[mi][ni][r] = 0.f;

    const unsigned* Abase = sA + (wm * 32 + g) * SA + tg;
    const unsigned* Bb    = g_we_sw + wn * 64 + g * 8;

    #pragma unroll 2
    for (int ks = 0; ks < EDIM / 8; ks++) {
        const int k0 = ks * 8;
        unsigned a[2][4];
        #pragma unroll
        for (int mi = 0; mi < 2; mi++) {
            const unsigned* ap = Abase + mi * 16 * SA + k0;
            a[mi][0] = ap[0];
            a[mi][1] = ap[8 * SA];
            a[mi][2] = ap[4];
            a[mi][3] = ap[8 * SA + 4];
        }
        const uint4* p0 = (const uint4*)(Bb + (k0 + tg) * D);
        const uint4* p1 = (const uint4*)(Bb + (k0 + tg + 4) * D);
        const uint4 b0lo = __ldg(p0), b0hi = __ldg(p0 + 1);
        const uint4 b1lo = __ldg(p1), b1hi = __ldg(p1 + 1);
        const unsigned b0[8] = {b0lo.x, b0lo.y, b0lo.z, b0lo.w,
                                b0hi.x, b0hi.y, b0hi.z, b0hi.w};
        const unsigned b1[8] = {b1lo.x, b1lo.y, b1lo.z, b1lo.w,
                                b1hi.x, b1hi.y, b1hi.z, b1hi.w};
        #pragma unroll
        for (int ni = 0; ni < 8; ni++) {
            mma_tf32(acc[0][ni], a[0], b0[ni], b1[ni]);
            mma_tf32(acc[1][ni], a[1], b0[ni], b1[ni]);
        }
    }

    // write e tile to gmem as half2
    #pragma unroll
    for (int mi = 0; mi < 2; mi++) {
        const int r0 = wm * 32 + mi * 16 + g;
        #pragma unroll
        for (int ni = 0; ni < 8; ni++) {
            const int h = wn * 32 + ni * 4 + tg;   // half2 index within 64-wide row
            if (e0 + r0 < NE)
                g_e[(size_t)(e0 + r0) * 64 + h] =
                    __floats2half2_rn(acc[mi][ni][0], acc[mi][ni][1]);
            if (e0 + r0 + 8 < NE)
                g_e[(size_t)(e0 + r0 + 8) * 64 + h] =
                    __floats2half2_rn(acc[mi][ni][2], acc[mi][ni][3]);
        }
    }
}

// ---- E2: attention epilogue. Warp handles 8 edges; lane owns 4 cols. ----
__global__ __launch_bounds__(256) void epilogue_kernel(
    const void* __restrict__ ei_raw)
{
    const int tid  = threadIdx.x;
    const int w    = tid >> 5, lane = tid & 31;
    const int col  = lane * 4;
    const int e0   = blockIdx.x * 64 + w * 8;

    #pragma unroll 2
    for (int ii = 0; ii < 8; ii++) {
        const int eg = e0 + ii;
        if (eg < NE) {
            int src, dst;
            if (g_idx64) {
                const long long* p = (const long long*)ei_raw;
                src = (int)__ldg(p + eg); dst = (int)__ldg(p + NE + eg);
            } else {
                const int* p = (const int*)ei_raw;
                src = __ldg(p + eg); dst = __ldg(p + NE + eg);
            }
            // fp16 e: lane reads 2 half2 (8 bytes, coalesced)
            const __half2* eh = g_e + (size_t)eg * 64 + 2 * lane;
            const float2 e01 = __half22float2(__ldg(eh));
            const float2 e23 = __half22float2(__ldg(eh + 1));

            const float4 qi = *(const float4*)(g_q + (size_t)dst * D + col);
            float4 kj = *(const float4*)(g_k + (size_t)src * D + col);
            float4 vj = *(const float4*)(g_v + (size_t)src * D + col);
            kj.x += e01.x; kj.y += e01.y; kj.z += e23.x; kj.w += e23.y;
            vj.x += e01.x; vj.y += e01.y; vj.z += e23.x; vj.w += e23.y;

            float p = qi.x * kj.x + qi.y * kj.y + qi.z * kj.z + qi.w * kj.w;
            p += __shfl_xor_sync(0xffffffffu, p, 1);
            p += __shfl_xor_sync(0xffffffffu, p, 2);
            p += __shfl_xor_sync(0xffffffffu, p, 4);
            p += __shfl_xor_sync(0xffffffffu, p, 8);
            const float ex = expf(p * 0.125f);   // 1/sqrt(64); exact softmax w/o max-sub

            red_v4(g_agg + (size_t)dst * D + col,
                   ex * vj.x, ex * vj.y, ex * vj.z, ex * vj.w);
            if ((lane & 15) == 0)
                red_1(&g_sum[dst * 2 + (lane >> 4)], ex);
        }
    }
}

__global__ void finalize_kernel(float* __restrict__ out) {
    int idx = blockIdx.x * blockDim.x + threadIdx.x;
    if (idx >= NN * 32) return;
    const int n = idx >> 5;
    const int h = (idx & 31) >> 4;
    const float inv = 1.0f / (g_sum[n * 2 + h] + 1e-16f);
    float4 a = ((const float4*)g_agg)[idx];
    float4 o = ((float4*)out)[idx];
    o.x += a.x * inv; o.y += a.y * inv; o.z += a.z * inv; o.w += a.w * inv;
    ((float4*)out)[idx] = o;
}

extern "C" void kernel_launch(void* const* d_in, const int* in_sizes, int n_in,
                              void* d_out, int out_size) {
    const float* x           = (const float*)d_in[0];
    const float* last_update = (const float*)d_in[1];
    const void*  ei          = d_in[2];
    const float* t           = (const float*)d_in[3];
    const float* msg         = (const float*)d_in[4];
    const float* time_w      = (const float*)d_in[5];
    const float* time_b      = (const float*)d_in[6];
    const float* Wq          = (const float*)d_in[7];
    const float* bq          = (const float*)d_in[8];
    const float* Wk          = (const float*)d_in[9];
    const float* bk          = (const float*)d_in[10];
    const float* Wv          = (const float*)d_in[11];
    const float* bv          = (const float*)d_in[12];
    const float* We          = (const float*)d_in[13];
    const float* Ws          = (const float*)d_in[14];
    const float* bs          = (const float*)d_in[15];
    float* out = (float*)d_out;

    const int smem_e1 = TE * SA * 4;     // 83,968 bytes
    const int smem_px = 128 * SX * 4;    // 67,584 bytes
    static int configured = 0;
    if (!configured) {
        cudaFuncSetAttribute(egemm_kernel,
                             cudaFuncAttributeMaxDynamicSharedMemorySize, smem_e1);
        cudaFuncSetAttribute(proj_kernel,
                             cudaFuncAttributeMaxDynamicSharedMemorySize, smem_px);
        configured = 1;
    }

    detect_kernel<<<1, 32>>>((const long long*)ei);
    swizzle_we_kernel<<<(EDIM * D + 255) / 256, 256>>>(We);
    swizzle_w_kernel<<<(4 * D * D + 255) / 256, 256>>>(Wq, Wk, Wv, Ws);
    zero_kernel<<<(NN * D + 255) / 256, 256>>>();
    proj_kernel<<<dim3((NN + 127) / 128, 4), 256, smem_px>>>(x, bq, bk, bv, bs, out);
    egemm_kernel<<<(NE + TE - 1) / TE, 256, smem_e1>>>(ei, last_update, t, msg,
                                                       time_w, time_b);
    epilogue_kernel<<<(NE + 63) / 64, 256>>>(ei);
    finalize_kernel<<<(NN * 32 + 255) / 256, 256>>>(out);
}